// round 15
// baseline (speedup 1.0000x reference)
#include <cuda_runtime.h>
#include <cuda_bf16.h>
#include <cstdint>

#define BB 4
#define NN 4096
#define CC 256
#define CK 32

// bf16 hi/lo split scratch (device globals = legal scratch)
__device__ __nv_bfloat16 d_Fhi[BB * NN * CK], d_Flo[BB * NN * CK];
__device__ __nv_bfloat16 d_Ghi[BB * NN * CK], d_Glo[BB * NN * CK];
__device__ __nv_bfloat16 d_Hhi[(size_t)BB * NN * CC], d_Hlo[(size_t)BB * NN * CC];

// ------------------------- helpers -------------------------
__device__ __forceinline__ uint32_t smem_u32(const void* p) {
    uint32_t a;
    asm("{ .reg .u64 t; cvta.to.shared.u64 t, %1; cvt.u32.u64 %0, t; }" : "=r"(a) : "l"(p));
    return a;
}
__device__ __forceinline__ void ldsm4(uint32_t* r, uint32_t a) {
    asm volatile("ldmatrix.sync.aligned.m8n8.x4.shared.b16 {%0,%1,%2,%3}, [%4];"
        : "=r"(r[0]), "=r"(r[1]), "=r"(r[2]), "=r"(r[3]) : "r"(a));
}
__device__ __forceinline__ void ldsm4t(uint32_t* r, uint32_t a) {
    asm volatile("ldmatrix.sync.aligned.m8n8.x4.trans.shared.b16 {%0,%1,%2,%3}, [%4];"
        : "=r"(r[0]), "=r"(r[1]), "=r"(r[2]), "=r"(r[3]) : "r"(a));
}
__device__ __forceinline__ void mma_bf16(float* d, const uint32_t* a, uint32_t b0, uint32_t b1) {
    asm volatile("mma.sync.aligned.m16n8k16.row.col.f32.bf16.bf16.f32 "
        "{%0,%1,%2,%3}, {%4,%5,%6,%7}, {%8,%9}, {%0,%1,%2,%3};"
        : "+f"(d[0]), "+f"(d[1]), "+f"(d[2]), "+f"(d[3])
        : "r"(a[0]), "r"(a[1]), "r"(a[2]), "r"(a[3]), "r"(b0), "r"(b1));
}
__device__ __forceinline__ void cpasync16(uint32_t saddr, const void* g) {
    asm volatile("cp.async.cg.shared.global [%0], [%1], 16;" :: "r"(saddr), "l"(g));
}
#define CP_COMMIT() asm volatile("cp.async.commit_group;")
#define CP_WAIT0()  asm volatile("cp.async.wait_group 0;" ::: "memory")
#define STS32(a, v) asm volatile("st.shared.b32 [%0], %1;" :: "r"(a), "r"(v) : "memory")

__device__ __forceinline__ void bsplit(float v, __nv_bfloat16& hi, __nv_bfloat16& lo) {
    hi = __float2bfloat16(v);
    lo = __float2bfloat16(v - __bfloat162float(hi));
}

// packed f32x2 (for proj)
__device__ __forceinline__ unsigned long long pack2(float lo, float hi) {
    unsigned long long r;
    asm("mov.b64 %0, {%1, %2};" : "=l"(r) : "f"(lo), "f"(hi));
    return r;
}
__device__ __forceinline__ void unpack2(unsigned long long v, float& lo, float& hi) {
    asm("mov.b64 {%0, %1}, %2;" : "=f"(lo), "=f"(hi) : "l"(v));
}
__device__ __forceinline__ void fma2(unsigned long long& d, unsigned long long a,
                                     unsigned long long b) {
    asm("fma.rn.f32x2 %0, %1, %2, %3;" : "=l"(d) : "l"(a), "l"(b), "l"(d));
}

// ---- flash5 smem layout (bytes). G/F/P pitch 80, H pitch 528 ----
// F per component = 32 rows x 80 = 2560; per buffer (hi+lo) = 5120; 3 bufs.
#define OFF_G    0        // 64 rows hi +0, lo +5120             (10240)
#define OFF_P    10240    // + pbuf*5120 (Phi only, 2 bufs)      (10240)
#define OFF_LRED 20480    // 64 floats                           (256 pad)
#define OFF_F    20736    // + fbuf*5120; hi +0, lo +2560 (3 bufs, 15360)
#define OFF_H    36096    // + hbuf*33792; hi +0, lo +16896 (3 bufs, 101376)
#define SMEM5    137472

// =====================================================================
// Kernel 1: projections -> bf16 hi/lo splits (f32x2 packed inner loop)
// =====================================================================
__global__ __launch_bounds__(256) void proj_kernel(
    const float* __restrict__ x,
    const float* __restrict__ Wf, const float* __restrict__ bfv,
    const float* __restrict__ Wg, const float* __restrict__ bgv,
    const float* __restrict__ Wh, const float* __restrict__ bhv)
{
    __shared__ float xs[64][64];
    __shared__ float ws[64][64];

    const int t = threadIdx.x;
    const int pix0 = blockIdx.x * 64;
    const int pg = t >> 4;
    const int og = t & 15;

    for (int oc = 0; oc < 5; oc++) {
        unsigned long long accp[4][2];
#pragma unroll
        for (int i = 0; i < 4; i++) { accp[i][0] = 0ull; accp[i][1] = 0ull; }

        for (int kc = 0; kc < 4; kc++) {
            __syncthreads();
            for (int i = t; i < 1024; i += 256) {
                int px = i >> 4;
                int kq = i & 15;
                *(float4*)&xs[px][kq * 4] =
                    *(const float4*)&x[(size_t)(pix0 + px) * CC + kc * 64 + kq * 4];
            }
            for (int i = t; i < 4096; i += 256) {
                int k = i >> 6;
                int o = i & 63;
                int kg = kc * 64 + k;
                float v;
                if (oc == 0)
                    v = (o < 32) ? Wf[kg * CK + o] : Wg[kg * CK + (o - 32)];
                else
                    v = Wh[kg * CC + (oc - 1) * 64 + o];
                ws[k][o] = v;
            }
            __syncthreads();

#pragma unroll 8
            for (int k = 0; k < 64; k++) {
                float4 wv = *(const float4*)&ws[k][og * 4];
                unsigned long long wp0 = pack2(wv.x, wv.y);
                unsigned long long wp1 = pack2(wv.z, wv.w);
#pragma unroll
                for (int i = 0; i < 4; i++) {
                    float xv = xs[pg * 4 + i][k];
                    unsigned long long xp = pack2(xv, xv);
                    fma2(accp[i][0], xp, wp0);
                    fma2(accp[i][1], xp, wp1);
                }
            }
        }

#pragma unroll
        for (int i = 0; i < 4; i++) {
            int px = pix0 + pg * 4 + i;
            float a0, a1, a2, a3;
            unpack2(accp[i][0], a0, a1);
            unpack2(accp[i][1], a2, a3);
            float av[4] = {a0, a1, a2, a3};
#pragma unroll
            for (int j = 0; j < 4; j++) {
                int o = og * 4 + j;
                __nv_bfloat16 hi, lo;
                if (oc == 0) {
                    if (o < 32) {
                        bsplit(av[j] + bfv[o], hi, lo);
                        d_Fhi[px * CK + o] = hi; d_Flo[px * CK + o] = lo;
                    } else {
                        bsplit(av[j] + bgv[o - 32], hi, lo);
                        d_Ghi[px * CK + o - 32] = hi; d_Glo[px * CK + o - 32] = lo;
                    }
                } else {
                    int oo = (oc - 1) * 64 + o;
                    bsplit(av[j] + bhv[oo], hi, lo);
                    d_Hhi[(size_t)px * CC + oo] = hi; d_Hlo[(size_t)px * CC + oo] = lo;
                }
            }
        }
    }
}

// =====================================================================
// tile loader (512 threads): F (32x32 hi/lo) + H (32x256 hi/lo), JT=32
// =====================================================================
__device__ __forceinline__ void load_tile(uint32_t sb, int buf, size_t bpix, int j0, int t)
{
    uint32_t hb = sb + OFF_H + buf * 33792;
#pragma unroll
    for (int i = 0; i < 4; i++) {
        int id = t + 512 * i;
        int hl = id >> 10, r = (id >> 5) & 31, c = id & 31;
        const __nv_bfloat16* s = (hl ? d_Hlo : d_Hhi) + (bpix + j0 + r) * CC + c * 8;
        cpasync16(hb + hl * 16896 + (uint32_t)r * 528 + c * 16, s);
    }
    if (t < 256) {
        int hl = t >> 7, r = (t >> 2) & 31, c = t & 3;
        const __nv_bfloat16* s = (hl ? d_Flo : d_Fhi) + (bpix + j0 + r) * CK + c * 8;
        cpasync16(sb + OFF_F + buf * 5120 + hl * 2560 + (uint32_t)r * 80 + c * 16, s);
    }
}

// =====================================================================
// Kernel 2: flash5. CTA = 64 q, 16 warps, JT=32, 128 tiles, lagged PV.
// QK (all warps): warp -> (16q mt=w&3) x (8j n8=w>>2), 3-term split.
// PV (all warps): warp -> (32q qh=w&1) x (32ch cs=w>>1), 2-term
//   (P bf16 hi only; l = sum of bf16-rounded e for consistent softmax).
// One __syncthreads per tile; F/H triple-buffered, Phi double-buffered.
// =====================================================================
__global__ __launch_bounds__(512, 1) void flash5(
    const float* __restrict__ x, float* __restrict__ out)
{
    extern __shared__ char sm[];
    const uint32_t sb = smem_u32(sm);
    const int t = threadIdx.x;
    const int w = t >> 5, l = t & 31;
    const int b = blockIdx.x >> 6, qt = blockIdx.x & 63;
    const size_t bpix = (size_t)b * NN;
    const size_t qpix = bpix + qt * 64;
    const int sel = l >> 3;
    const int mt = w & 3, n8 = w >> 2;      // QK mapping
    const int qh = w & 1, cs = w >> 1;      // PV mapping: 32q half, 32ch slice

    // prologue: G (persistent) + tile 0
    {
        int hl = t >> 8, r = (t >> 2) & 63, c = t & 3;
        const __nv_bfloat16* s = (hl ? d_Glo : d_Ghi) + (qpix + r) * CK + c * 8;
        cpasync16(sb + OFF_G + hl * 5120 + (uint32_t)r * 80 + c * 16, s);
    }
    load_tile(sb, 0, bpix, 0, t);
    CP_COMMIT();
    CP_WAIT0();
    __syncthreads();

    float* lred = (float*)(sm + OFF_LRED);
    if (t < 64) lred[t] = 0.f;

    // persistent G A-fragments (q rows mt*16..+15, k 0..31)
    uint32_t aGh[2][4], aGl[2][4];
#pragma unroll
    for (int ks = 0; ks < 2; ks++) {
        uint32_t roff = (uint32_t)(mt * 16 + (sel & 1) * 8 + (l & 7)) * 80 + ks * 32 + (sel >> 1) * 16;
        ldsm4(aGh[ks], sb + OFF_G + roff);
        ldsm4(aGl[ks], sb + OFF_G + 5120 + roff);
    }

    // start tile-1 load
    load_tile(sb, 1, bpix, 32, t);
    CP_COMMIT();

    float O[2][4][4];     // [m2 of 32q][nt of 4x8ch][frag]
#pragma unroll
    for (int i = 0; i < 2; i++)
#pragma unroll
        for (int j = 0; j < 4; j++)
#pragma unroll
            for (int k = 0; k < 4; k++) O[i][j][k] = 0.f;
    float lacc0 = 0.f, lacc1 = 0.f;

    const uint32_t qk_roff = (uint32_t)(n8 * 8 + (l & 7)) * 80 + sel * 16;
    const uint32_t p_colb  = (uint32_t)(n8 * 8 + (l & 3) * 2) * 2;
    const int p_r0 = mt * 16 + (l >> 2);

    // QK(0) + exp -> Phi buf 0
    {
        uint32_t bFh[4], bFl[4];
        ldsm4(bFh, sb + OFF_F + qk_roff);
        ldsm4(bFl, sb + OFF_F + 2560 + qk_roff);
        float d[4] = {0.f, 0.f, 0.f, 0.f};
#pragma unroll
        for (int ks = 0; ks < 2; ks++) {
            mma_bf16(d, aGh[ks], bFh[ks * 2], bFh[ks * 2 + 1]);
            mma_bf16(d, aGh[ks], bFl[ks * 2], bFl[ks * 2 + 1]);
            mma_bf16(d, aGl[ks], bFh[ks * 2], bFh[ks * 2 + 1]);
        }
        __nv_bfloat16 h0 = __float2bfloat16(__expf(d[0]));
        __nv_bfloat16 h1 = __float2bfloat16(__expf(d[1]));
        __nv_bfloat16 h2 = __float2bfloat16(__expf(d[2]));
        __nv_bfloat16 h3 = __float2bfloat16(__expf(d[3]));
        lacc0 += __bfloat162float(h0) + __bfloat162float(h1);
        lacc1 += __bfloat162float(h2) + __bfloat162float(h3);
        uint32_t pb = sb + OFF_P;
        STS32(pb + (uint32_t)p_r0 * 80 + p_colb,
              ((uint32_t)__bfloat16_as_ushort(h1) << 16) | __bfloat16_as_ushort(h0));
        STS32(pb + (uint32_t)(p_r0 + 8) * 80 + p_colb,
              ((uint32_t)__bfloat16_as_ushort(h3) << 16) | __bfloat16_as_ushort(h2));
    }

    int cur = 0, nxt = 1, nx2 = 2;

#pragma unroll 1
    for (int tile = 0; tile < 128; tile++) {
        CP_WAIT0();
        __syncthreads();
        if (tile + 2 < 128) {
            load_tile(sb, nx2, bpix, (tile + 2) * 32, t);
            CP_COMMIT();
        }

        // ---- QK(tile+1): S[16q x 8j] per warp, 3-term ----
        float d[4] = {0.f, 0.f, 0.f, 0.f};
        if (tile + 1 < 128) {
            uint32_t fb = sb + OFF_F + nxt * 5120;
            uint32_t bFh[4], bFl[4];
            ldsm4(bFh, fb + qk_roff);
            ldsm4(bFl, fb + 2560 + qk_roff);
#pragma unroll
            for (int ks = 0; ks < 2; ks++) {
                mma_bf16(d, aGh[ks], bFh[ks * 2], bFh[ks * 2 + 1]);
                mma_bf16(d, aGh[ks], bFl[ks * 2], bFl[ks * 2 + 1]);
                mma_bf16(d, aGl[ks], bFh[ks * 2], bFh[ks * 2 + 1]);
            }
        }

        // ---- PV(tile): O[32q x 32ch] += Phi . (Hhi + Hlo) ----
        {
            uint32_t hb = sb + OFF_H + cur * 33792;
            uint32_t pbase = sb + OFF_P + (tile & 1) * 5120;
            uint32_t bHh[2][2][4], bHl[2][2][4];
#pragma unroll
            for (int ks = 0; ks < 2; ks++)
#pragma unroll
                for (int nc = 0; nc < 2; nc++) {
                    uint32_t roff = (uint32_t)(ks * 16 + (sel & 1) * 8 + (l & 7)) * 528 +
                                    (cs * 32 + nc * 16) * 2 + (sel >> 1) * 16;
                    ldsm4t(bHh[ks][nc], hb + roff);
                    ldsm4t(bHl[ks][nc], hb + 16896 + roff);
                }
            uint32_t aP[2][2][4];
#pragma unroll
            for (int m2 = 0; m2 < 2; m2++)
#pragma unroll
                for (int ks = 0; ks < 2; ks++) {
                    uint32_t roff = (uint32_t)(qh * 32 + m2 * 16 + (sel & 1) * 8 + (l & 7)) * 80 +
                                    ks * 32 + (sel >> 1) * 16;
                    ldsm4(aP[m2][ks], pbase + roff);
                }
#pragma unroll
            for (int m2 = 0; m2 < 2; m2++)
#pragma unroll
                for (int nt = 0; nt < 4; nt++) {
                    int nc = nt >> 1, o2 = (nt & 1) * 2;
#pragma unroll
                    for (int ks = 0; ks < 2; ks++) {
                        mma_bf16(O[m2][nt], aP[m2][ks], bHh[ks][nc][o2], bHh[ks][nc][o2 + 1]);
                        mma_bf16(O[m2][nt], aP[m2][ks], bHl[ks][nc][o2], bHl[ks][nc][o2 + 1]);
                    }
                }
        }

        // ---- exp(tile+1) -> Phi[(tile+1)&1] ----
        if (tile + 1 < 128) {
            __nv_bfloat16 h0 = __float2bfloat16(__expf(d[0]));
            __nv_bfloat16 h1 = __float2bfloat16(__expf(d[1]));
            __nv_bfloat16 h2 = __float2bfloat16(__expf(d[2]));
            __nv_bfloat16 h3 = __float2bfloat16(__expf(d[3]));
            lacc0 += __bfloat162float(h0) + __bfloat162float(h1);
            lacc1 += __bfloat162float(h2) + __bfloat162float(h3);
            uint32_t pb = sb + OFF_P + ((tile + 1) & 1) * 5120;
            STS32(pb + (uint32_t)p_r0 * 80 + p_colb,
                  ((uint32_t)__bfloat16_as_ushort(h1) << 16) | __bfloat16_as_ushort(h0));
            STS32(pb + (uint32_t)(p_r0 + 8) * 80 + p_colb,
                  ((uint32_t)__bfloat16_as_ushort(h3) << 16) | __bfloat16_as_ushort(h2));
        }

        int tmp = cur; cur = nxt; nxt = nx2; nx2 = tmp;
    }

    // ---- l reduction (QK mapping): quad shuffle + atomic ----
    lacc0 += __shfl_xor_sync(0xffffffffu, lacc0, 1);
    lacc0 += __shfl_xor_sync(0xffffffffu, lacc0, 2);
    lacc1 += __shfl_xor_sync(0xffffffffu, lacc1, 1);
    lacc1 += __shfl_xor_sync(0xffffffffu, lacc1, 2);
    if ((l & 3) == 0) {
        atomicAdd(&lred[mt * 16 + (l >> 2)], lacc0);
        atomicAdd(&lred[mt * 16 + (l >> 2) + 8], lacc1);
    }
    __syncthreads();

    // ---- epilogue (PV mapping): normalize + residual ----
#pragma unroll
    for (int m2 = 0; m2 < 2; m2++) {
        int r0 = qh * 32 + m2 * 16 + (l >> 2), r1 = r0 + 8;
        float i0 = 1.0f / lred[r0], i1 = 1.0f / lred[r1];
#pragma unroll
        for (int nt = 0; nt < 4; nt++) {
            int col = cs * 32 + nt * 8 + (l & 3) * 2;
            size_t p0 = (qpix + r0) * CC + col;
            size_t p1 = (qpix + r1) * CC + col;
            float2 xv0 = *(const float2*)&x[p0];
            float2 xv1 = *(const float2*)&x[p1];
            float2 ov0, ov1;
            ov0.x = xv0.x + O[m2][nt][0] * i0;
            ov0.y = xv0.y + O[m2][nt][1] * i0;
            ov1.x = xv1.x + O[m2][nt][2] * i1;
            ov1.y = xv1.y + O[m2][nt][3] * i1;
            *(float2*)&out[p0] = ov0;
            *(float2*)&out[p1] = ov1;
        }
    }
}

// =====================================================================
extern "C" void kernel_launch(void* const* d_in, const int* in_sizes, int n_in,
                              void* d_out, int out_size)
{
    const float* x  = (const float*)d_in[0];
    const float* Wf = (const float*)d_in[1];
    const float* bf = (const float*)d_in[2];
    const float* Wg = (const float*)d_in[3];
    const float* bg = (const float*)d_in[4];
    const float* Wh = (const float*)d_in[5];
    const float* bh = (const float*)d_in[6];
    float* out = (float*)d_out;

    cudaFuncSetAttribute(flash5, cudaFuncAttributeMaxDynamicSharedMemorySize, SMEM5);

    proj_kernel<<<BB * NN / 64, 256>>>(x, Wf, bf, Wg, bg, Wh, bh);
    flash5<<<BB * NN / 64, 512, SMEM5>>>(x, out);
}